// round 14
// baseline (speedup 1.0000x reference)
#include <cuda_runtime.h>
#include <cuda_bf16.h>
#include <math.h>
#include <stdint.h>

#define NTHREADS 512
#define SXSTR 68            // fp32 row stride (floats)
#define ASTR_B 272          // bf16 row stride in BYTES (136 bf16; 272%16==0 for ldmatrix)

// ---- byte offsets ----
#define AH_B 0              // A_hi  [256][136] bf16 = 69632 B
#define AL_B 69632          // A_lo
#define WH_B 139264         // W_hi  [128 k-rows][136 bf16] = 34816 B (K-MAJOR); W1_hi rows 0..63 in stage 1
#define WL_B 174080         // W_lo  (ends 208896)
// ---- float offsets ----
#define SX_F   34816        // fp32 [256][68] overlay on W region (written AFTER W1 reads complete)
#define PAR2_F 52224        // b2|g2|be2 (384 floats)
#define PAR3_F 52608        // b3|g3|be3
#define SRED_F 52992        // 1536: top2 partials / LN psums; pstg (896) aliases this in stage 1
#define SFIN_F 54528        // 192: final top-2 per channel
#define WMAX_F 54720        // 1024: per-warp column maxima
#define SMEM_FLOATS 55744
#define SMEM_BYTES (SMEM_FLOATS*4)   // 222976

// ---- pre-converted weights (global scratch; layout mirrors smem W region) ----
// [k][136] bf16, row stride 272 B; pad cols zero (zero-init of __device__ globals)
__device__ __align__(16) uint16_t gW1h[64 * 136];
__device__ __align__(16) uint16_t gW1l[64 * 136];
__device__ __align__(16) uint16_t gW2h[128 * 136];
__device__ __align__(16) uint16_t gW2l[128 * 136];
__device__ __align__(16) uint16_t gW3h[128 * 136];
__device__ __align__(16) uint16_t gW3l[128 * 136];

__device__ __forceinline__ uint32_t smem_u32(const void* p) {
    uint32_t a;
    asm("{ .reg .u64 t; cvta.to.shared.u64 t, %1; cvt.u32.u64 %0, t; }" : "=r"(a) : "l"(p));
    return a;
}
__device__ __forceinline__ void ldm4(uint32_t& r0, uint32_t& r1, uint32_t& r2, uint32_t& r3, uint32_t a) {
    asm volatile("ldmatrix.sync.aligned.m8n8.x4.shared.b16 {%0,%1,%2,%3}, [%4];"
                 : "=r"(r0), "=r"(r1), "=r"(r2), "=r"(r3) : "r"(a));
}
__device__ __forceinline__ void ldm4t(uint32_t& r0, uint32_t& r1, uint32_t& r2, uint32_t& r3, uint32_t a) {
    asm volatile("ldmatrix.sync.aligned.m8n8.x4.trans.shared.b16 {%0,%1,%2,%3}, [%4];"
                 : "=r"(r0), "=r"(r1), "=r"(r2), "=r"(r3) : "r"(a));
}
__device__ __forceinline__ void mma16816(float* c, const uint32_t* A, const uint32_t* B) {
    asm volatile("mma.sync.aligned.m16n8k16.row.col.f32.bf16.bf16.f32 "
                 "{%0,%1,%2,%3},{%4,%5,%6,%7},{%8,%9},{%0,%1,%2,%3};"
                 : "+f"(c[0]), "+f"(c[1]), "+f"(c[2]), "+f"(c[3])
                 : "r"(A[0]), "r"(A[1]), "r"(A[2]), "r"(A[3]), "r"(B[0]), "r"(B[1]));
}
__device__ __forceinline__ uint32_t pack2(float a, float b) {
    __nv_bfloat162 t = __floats2bfloat162_rn(a, b);
    uint32_t r; memcpy(&r, &t, 4); return r;
}
__device__ __forceinline__ float bfr(float v) {
    return __bfloat162float(__float2bfloat16(v));
}
__device__ __forceinline__ uint16_t bfbits(float v) {
    __nv_bfloat16 h = __float2bfloat16(v);
    uint16_t b; memcpy(&b, &h, 2); return b;
}

// ---- prep: convert W1/W2/W3 fp32 -> bf16 hi/lo in the smem-mirror layout ----
__global__ void prep_weights_kernel(const float* __restrict__ W1,
                                    const float* __restrict__ W2,
                                    const float* __restrict__ W3)
{
    int t = blockIdx.x * blockDim.x + threadIdx.x;
    int n = gridDim.x * blockDim.x;
    for (int i = t; i < 4096; i += n) {          // W1 [64][64]
        int k = i >> 6, o = i & 63;
        float v = W1[i];
        float h = bfr(v);
        gW1h[k * 136 + o] = bfbits(v);
        gW1l[k * 136 + o] = bfbits(v - h);
    }
    for (int i = t; i < 16384; i += n) {         // W2 [128][128]
        int k = i >> 7, o = i & 127;
        float v = W2[i];
        float h = bfr(v);
        gW2h[k * 136 + o] = bfbits(v);
        gW2l[k * 136 + o] = bfbits(v - h);
    }
    for (int i = t; i < 16384; i += n) {         // W3 [128][128]
        int k = i >> 7, o = i & 127;
        float v = W3[i];
        float h = bfr(v);
        gW3h[k * 136 + o] = bfbits(v);
        gW3l[k * 136 + o] = bfbits(v - h);
    }
}

__global__ __launch_bounds__(NTHREADS, 1)
void localgraph_fused_kernel(
    const float* __restrict__ inp,
    const float* __restrict__ W0, const float* __restrict__ b0, const float* __restrict__ g0, const float* __restrict__ be0,
    const float* __restrict__ b1, const float* __restrict__ g1, const float* __restrict__ be1,
    const float* __restrict__ b2, const float* __restrict__ g2, const float* __restrict__ be2,
    const float* __restrict__ b3, const float* __restrict__ g3, const float* __restrict__ be3,
    float* __restrict__ out)
{
    extern __shared__ float smem[];
    char*  smc  = reinterpret_cast<char*>(smem);
    float* sx   = smem + SX_F;          // [256][68] fp32
    float* pstg = smem + SRED_F;        // stage-1 weights/params (aliases sred; dead before top-2)
    float* par2 = smem + PAR2_F;
    float* par3 = smem + PAR3_F;
    float* sred = smem + SRED_F;
    float* sfin = smem + SFIN_F;
    float* wmax = smem + WMAX_F;

    const uint32_t smb = smem_u32(smem);
    const int tid  = threadIdx.x;
    const int bm   = blockIdx.x;
    const int lane = tid & 31;
    const int w    = tid >> 5;
    const int lg = lane >> 3, lr = lane & 7;
    const int tq = lane & 3, tr = lane >> 2;

    // ======== STAGE 1 staging ========
    for (int i = tid; i < 512; i += NTHREADS) pstg[i] = W0[i];
    if (tid < 64) { pstg[512+tid]=b0[tid]; pstg[576+tid]=g0[tid]; pstg[640+tid]=be0[tid]; }
    if (tid >= 64 && tid < 128) {
        int i = tid - 64;
        pstg[704+i]=b1[i]; pstg[768+i]=g1[i]; pstg[832+i]=be1[i];
    }
    {   // W1 bf16 hi/lo: straight 16B copy from pre-converted buffers (rows 0..63)
        const uint4* s1h = reinterpret_cast<const uint4*>(gW1h);
        const uint4* s1l = reinterpret_cast<const uint4*>(gW1l);
        uint4* dH = reinterpret_cast<uint4*>(smc + WH_B);
        uint4* dL = reinterpret_cast<uint4*>(smc + WL_B);
        for (int i = tid; i < 1088; i += NTHREADS) { dH[i] = s1h[i]; dL[i] = s1l[i]; }
    }

    // stage-1 scalar decomposition: warp w owns nodes 16w..16w+15
    const int sg  = lane >> 3;
    const int so8 = lane & 7;
    const int sco = 4 * so8;
    const int nb  = 16 * w + sg;        // thread's nodes: nb + 4j

    float x[4][8];
#pragma unroll
    for (int j = 0; j < 4; j++) {
        const float4* pa = reinterpret_cast<const float4*>(inp + ((size_t)bm * 256 + nb + 4*j) * 8);
        float4 a = pa[0], b = pa[1];
        x[j][0]=a.x; x[j][1]=a.y; x[j][2]=a.z; x[j][3]=a.w;
        x[j][4]=b.x; x[j][5]=b.y; x[j][6]=b.z; x[j][7]=b.w;
    }
    __syncthreads();

    // ---- mlp0 (scalar): 8 -> 64, LN, ReLU -> bf16 A hi/lo cols 0..63 ----
    {
        float h[4][8];
#pragma unroll
        for (int G = 0; G < 2; G++) {
            float4 b4 = *reinterpret_cast<const float4*>(&pstg[512 + 32*G + sco]);
#pragma unroll
            for (int j = 0; j < 4; j++) {
                h[j][4*G+0]=b4.x; h[j][4*G+1]=b4.y; h[j][4*G+2]=b4.z; h[j][4*G+3]=b4.w;
            }
        }
#pragma unroll
        for (int k = 0; k < 8; k++) {
#pragma unroll
            for (int G = 0; G < 2; G++) {
                float4 wv = *reinterpret_cast<const float4*>(&pstg[k*64 + 32*G + sco]);
#pragma unroll
                for (int j = 0; j < 4; j++) {
                    float a = x[j][k];
                    h[j][4*G+0] += a*wv.x; h[j][4*G+1] += a*wv.y;
                    h[j][4*G+2] += a*wv.z; h[j][4*G+3] += a*wv.w;
                }
            }
        }
#pragma unroll
        for (int j = 0; j < 4; j++) {
            float sU = 0.f;
#pragma unroll
            for (int i = 0; i < 8; i++) sU += h[j][i];
            sU += __shfl_xor_sync(0xffffffffu, sU, 1);
            sU += __shfl_xor_sync(0xffffffffu, sU, 2);
            sU += __shfl_xor_sync(0xffffffffu, sU, 4);
            float mu = sU * (1.0f/64.0f), vv = 0.f;
#pragma unroll
            for (int i = 0; i < 8; i++) { float d = h[j][i]-mu; vv += d*d; }
            vv += __shfl_xor_sync(0xffffffffu, vv, 1);
            vv += __shfl_xor_sync(0xffffffffu, vv, 2);
            vv += __shfl_xor_sync(0xffffffffu, vv, 4);
            float rs = rsqrtf(vv * (1.0f/64.0f) + 1e-5f);
            uint32_t rowoff = (uint32_t)(nb + 4*j) * ASTR_B;
#pragma unroll
            for (int G = 0; G < 2; G++) {
                float4 g4  = *reinterpret_cast<const float4*>(&pstg[576 + 32*G + sco]);
                float4 be4 = *reinterpret_cast<const float4*>(&pstg[640 + 32*G + sco]);
                float v0 = fmaxf((h[j][4*G+0]-mu)*rs*g4.x + be4.x, 0.f);
                float v1 = fmaxf((h[j][4*G+1]-mu)*rs*g4.y + be4.y, 0.f);
                float v2 = fmaxf((h[j][4*G+2]-mu)*rs*g4.z + be4.z, 0.f);
                float v3 = fmaxf((h[j][4*G+3]-mu)*rs*g4.w + be4.w, 0.f);
                uint32_t off = rowoff + (32*G + sco) * 2;
                *reinterpret_cast<uint2*>(smc + AH_B + off) =
                    make_uint2(pack2(v0, v1), pack2(v2, v3));
                *reinterpret_cast<uint2*>(smc + AL_B + off) =
                    make_uint2(pack2(v0 - bfr(v0), v1 - bfr(v1)),
                               pack2(v2 - bfr(v2), v3 - bfr(v3)));
            }
        }
    }
    __syncthreads();   // A cols 0..63 + W1 visible to all

    // ---- mlp1 (tensor): 64 -> 64, split-bf16; warp owns 16 nodes x 64 cols ----
    {
        const uint32_t aoff1 = smb + AH_B + (uint32_t)(16*w + ((lg&1)<<3) + lr) * ASTR_B + ((lg>>1)<<4);
        const uint32_t boff1 = smb + WH_B + (uint32_t)(((lg&1)<<3) + lr) * ASTR_B + ((lg>>1)<<4);
        float acc1[8][4];
#pragma unroll
        for (int nt = 0; nt < 8; nt++)
#pragma unroll
            for (int q = 0; q < 4; q++) acc1[nt][q] = 0.f;

#pragma unroll
        for (int ks = 0; ks < 4; ks++) {
            const uint32_t kb  = (uint32_t)ks * 32;
            const uint32_t kbw = (uint32_t)ks * 16 * ASTR_B;
            uint32_t Ah[4], Al[4];
            ldm4(Ah[0], Ah[1], Ah[2], Ah[3], aoff1 + kb);
            ldm4(Al[0], Al[1], Al[2], Al[3], aoff1 + (AL_B - AH_B) + kb);
#pragma unroll
            for (int p = 0; p < 4; p++) {
                uint32_t Bh[4], Bl[4];
                ldm4t(Bh[0], Bh[1], Bh[2], Bh[3], boff1 + kbw + (uint32_t)p*32);
                ldm4t(Bl[0], Bl[1], Bl[2], Bl[3], boff1 + (WL_B - WH_B) + kbw + (uint32_t)p*32);
                mma16816(acc1[2*p],   Ah, Bh);
                mma16816(acc1[2*p],   Ah, Bl);
                mma16816(acc1[2*p],   Al, Bh);
                mma16816(acc1[2*p+1], Ah, Bh + 2);
                mma16816(acc1[2*p+1], Ah, Bl + 2);
                mma16816(acc1[2*p+1], Al, Bh + 2);
            }
        }
        __syncthreads();   // ALL warps done reading W1 before sx (overlapping region) is written

        // epilogue: bias + LN (warp-local rows) + ReLU -> fp32 sx AND bf16 A
        float rS[2] = {0.f, 0.f}, rQ[2] = {0.f, 0.f};
#pragma unroll
        for (int nt = 0; nt < 8; nt++) {
            int col0 = nt*8 + 2*tq;
            float2 bb = *reinterpret_cast<const float2*>(&pstg[704 + col0]);
            float v00 = acc1[nt][0] + bb.x, v01 = acc1[nt][1] + bb.y;
            float v10 = acc1[nt][2] + bb.x, v11 = acc1[nt][3] + bb.y;
            acc1[nt][0]=v00; acc1[nt][1]=v01; acc1[nt][2]=v10; acc1[nt][3]=v11;
            rS[0]+=v00+v01; rS[1]+=v10+v11;
            rQ[0]+=v00*v00+v01*v01; rQ[1]+=v10*v10+v11*v11;
        }
#pragma unroll
        for (int rh = 0; rh < 2; rh++) {
            rS[rh] += __shfl_xor_sync(0xffffffffu, rS[rh], 1);
            rS[rh] += __shfl_xor_sync(0xffffffffu, rS[rh], 2);
            rQ[rh] += __shfl_xor_sync(0xffffffffu, rQ[rh], 1);
            rQ[rh] += __shfl_xor_sync(0xffffffffu, rQ[rh], 2);
        }
        float muv[2], rsv[2];
#pragma unroll
        for (int rh = 0; rh < 2; rh++) {
            float mu = rS[rh] * (1.0f/64.0f);
            muv[rh] = mu;
            rsv[rh] = rsqrtf(rQ[rh] * (1.0f/64.0f) - mu*mu + 1e-5f);
        }
        int node0 = 16*w + tr, node1 = node0 + 8;
#pragma unroll
        for (int nt = 0; nt < 8; nt++) {
            int col0 = nt*8 + 2*tq;
            float2 gg = *reinterpret_cast<const float2*>(&pstg[768 + col0]);
            float2 bb = *reinterpret_cast<const float2*>(&pstg[832 + col0]);
            float v00 = fmaxf((acc1[nt][0]-muv[0])*rsv[0]*gg.x + bb.x, 0.f);
            float v01 = fmaxf((acc1[nt][1]-muv[0])*rsv[0]*gg.y + bb.y, 0.f);
            float v10 = fmaxf((acc1[nt][2]-muv[1])*rsv[1]*gg.x + bb.x, 0.f);
            float v11 = fmaxf((acc1[nt][3]-muv[1])*rsv[1]*gg.y + bb.y, 0.f);
            *reinterpret_cast<float2*>(&sx[node0*SXSTR + col0]) = make_float2(v00, v01);
            *reinterpret_cast<float2*>(&sx[node1*SXSTR + col0]) = make_float2(v10, v11);
            uint32_t off0 = (uint32_t)node0 * ASTR_B + col0*2;
            uint32_t off1 = (uint32_t)node1 * ASTR_B + col0*2;
            *reinterpret_cast<uint32_t*>(smc + AH_B + off0) = pack2(v00, v01);
            *reinterpret_cast<uint32_t*>(smc + AH_B + off1) = pack2(v10, v11);
            *reinterpret_cast<uint32_t*>(smc + AL_B + off0) = pack2(v00 - bfr(v00), v01 - bfr(v01));
            *reinterpret_cast<uint32_t*>(smc + AL_B + off1) = pack2(v10 - bfr(v10), v11 - bfr(v11));
        }
    }
    __syncthreads();

    // ---- top-2 + argmax per channel over 256 nodes (reads fp32 sx) ----
    {
        const int ch = tid & 63, chunk = tid >> 6;
        float m1 = -INFINITY, m2 = -INFINITY; int i1 = -1;
        const int jb = chunk * 32;
        for (int j = 0; j < 32; j++) {
            float v = sx[(jb + j) * SXSTR + ch];
            if (v > m1)      { m2 = m1; m1 = v; i1 = jb + j; }
            else if (v > m2) { m2 = v; }
        }
        sred[chunk * 64 + ch]       = m1;
        sred[512 + chunk * 64 + ch] = m2;
        reinterpret_cast<int*>(sred)[1024 + chunk * 64 + ch] = i1;
    }
    __syncthreads();
    if (tid < 64) {
        float m1 = sred[tid], m2 = sred[512 + tid];
        int   i1 = reinterpret_cast<int*>(sred)[1024 + tid];
#pragma unroll
        for (int c = 1; c < 8; c++) {
            float a1 = sred[c * 64 + tid], a2 = sred[512 + c * 64 + tid];
            int   ai = reinterpret_cast<int*>(sred)[1024 + c * 64 + tid];
            if (a1 > m1) { m2 = fmaxf(m1, a2); m1 = a1; i1 = ai; }
            else         { m2 = fmaxf(m2, a1); }
        }
        sfin[tid] = m1; sfin[64 + tid] = m2;
        reinterpret_cast<int*>(sfin)[128 + tid] = i1;
    }
    __syncthreads();

    // ---- concat (excl half only): A cols 64..127 ----
    {
        const int crow = tid >> 1, chalf = tid & 1;
        const float* sr = sx + crow * SXSTR;
        const int cb = chalf * 32;
        char* ah = smc + AH_B + crow * ASTR_B + (64 + cb) * 2;
        char* al = smc + AL_B + crow * ASTR_B + (64 + cb) * 2;
#pragma unroll
        for (int c = 0; c < 32; c += 2) {
            int d = cb + c;
            float a0 = sr[d], a1 = sr[d+1];
            int   j0 = reinterpret_cast<int*>(sfin)[128 + d];
            int   j1 = reinterpret_cast<int*>(sfin)[128 + d + 1];
            float e0x = (j0 == crow) ? sfin[64 + d]     : sfin[d];
            float e1x = (j1 == crow) ? sfin[64 + d + 1] : sfin[d + 1];
            float v0 = fmaxf(e0x, a0 - 10000.0f);
            float v1 = fmaxf(e1x, a1 - 10000.0f);
            *reinterpret_cast<uint32_t*>(ah + c*2) = pack2(v0, v1);
            *reinterpret_cast<uint32_t*>(al + c*2) = pack2(v0 - bfr(v0), v1 - bfr(v1));
        }
    }
    __syncthreads();   // sx consumed; full A ready

    // ======== big layers: warp = (rb = w&7 node-block, cg = w>>3 col-group) ========
    const int rb = w & 7, cg = w >> 3, ob = cg * 64;
    const uint32_t aoff = smb + AH_B + (uint32_t)(rb*32 + ((lg&1)<<3) + lr) * ASTR_B + ((lg>>1)<<4);
    const uint32_t boff = smb + WH_B + (uint32_t)(((lg&1)<<3) + lr) * ASTR_B + (uint32_t)(ob*2 + ((lg>>1)<<4));
    float* psumS = sred;          // [512]
    float* psumQ = sred + 512;    // [512]

    float acc[2][8][4];

    for (int layer = 0; layer < 2; layer++) {
        const float* par = layer ? par3 : par2;
        // ---- W -> smem: straight 16B copy of pre-converted hi/lo ----
        {
            const uint4* sH = reinterpret_cast<const uint4*>(layer ? gW3h : gW2h);
            const uint4* sL = reinterpret_cast<const uint4*>(layer ? gW3l : gW2l);
            uint4* dH = reinterpret_cast<uint4*>(smc + WH_B);
            uint4* dL = reinterpret_cast<uint4*>(smc + WL_B);
            for (int i = tid; i < 2176; i += NTHREADS) { dH[i] = sH[i]; dL[i] = sL[i]; }
            if (tid < 128) {
                float* pdst = layer ? par3 : par2;
                pdst[tid]       = layer ? b3[tid]  : b2[tid];
                pdst[128 + tid] = layer ? g3[tid]  : g2[tid];
                pdst[256 + tid] = layer ? be3[tid] : be2[tid];
            }
        }
        __syncthreads();

        // ---- MMA: C[32 nodes][64 outs] via split-bf16 ----
#pragma unroll
        for (int mt = 0; mt < 2; mt++)
#pragma unroll
            for (int nt = 0; nt < 8; nt++)
#pragma unroll
                for (int q = 0; q < 4; q++) acc[mt][nt][q] = 0.f;

#pragma unroll
        for (int ks = 0; ks < 8; ks++) {
            const uint32_t kb  = (uint32_t)ks * 32;
            const uint32_t kbw = (uint32_t)ks * 16 * ASTR_B;
            uint32_t Ah[2][4], Al[2][4];
            ldm4(Ah[0][0], Ah[0][1], Ah[0][2], Ah[0][3], aoff + kb);
            ldm4(Ah[1][0], Ah[1][1], Ah[1][2], Ah[1][3], aoff + 16*ASTR_B + kb);
            ldm4(Al[0][0], Al[0][1], Al[0][2], Al[0][3], aoff + (AL_B - AH_B) + kb);
            ldm4(Al[1][0], Al[1][1], Al[1][2], Al[1][3], aoff + (AL_B - AH_B) + 16*ASTR_B + kb);
#pragma unroll
            for (int p = 0; p < 4; p++) {
                uint32_t Bh[4], Bl[4];
                ldm4t(Bh[0], Bh[1], Bh[2], Bh[3], boff + kbw + (uint32_t)p*32);
                ldm4t(Bl[0], Bl[1], Bl[2], Bl[3], boff + (WL_B - WH_B) + kbw + (uint32_t)p*32);
#pragma unroll
                for (int mt = 0; mt < 2; mt++) {
                    mma16816(acc[mt][2*p],   Ah[mt], Bh);
                    mma16816(acc[mt][2*p],   Ah[mt], Bl);
                    mma16816(acc[mt][2*p],   Al[mt], Bh);
                    mma16816(acc[mt][2*p+1], Ah[mt], Bh + 2);
                    mma16816(acc[mt][2*p+1], Ah[mt], Bl + 2);
                    mma16816(acc[mt][2*p+1], Al[mt], Bh + 2);
                }
            }
        }

        // ---- epilogue: bias, LN partial sums ----
        float rS[2][2] = {{0.f,0.f},{0.f,0.f}}, rQ[2][2] = {{0.f,0.f},{0.f,0.f}};
#pragma unroll
        for (int mt = 0; mt < 2; mt++) {
#pragma unroll
            for (int nt = 0; nt < 8; nt++) {
                int col0 = ob + nt*8 + 2*tq;
                float2 bb = *reinterpret_cast<const float2*>(&par[col0]);
                float v00 = acc[mt][nt][0] + bb.x, v01 = acc[mt][nt][1] + bb.y;
                float v10 = acc[mt][nt][2] + bb.x, v11 = acc[mt][nt][3] + bb.y;
                acc[mt][nt][0]=v00; acc[mt][nt][1]=v01; acc[mt][nt][2]=v10; acc[mt][nt][3]=v11;
                rS[mt][0]+=v00+v01; rS[mt][1]+=v10+v11;
                rQ[mt][0]+=v00*v00+v01*v01; rQ[mt][1]+=v10*v10+v11*v11;
            }
        }
#pragma unroll
        for (int mt = 0; mt < 2; mt++)
#pragma unroll
            for (int rh = 0; rh < 2; rh++) {
                rS[mt][rh] += __shfl_xor_sync(0xffffffffu, rS[mt][rh], 1);
                rS[mt][rh] += __shfl_xor_sync(0xffffffffu, rS[mt][rh], 2);
                rQ[mt][rh] += __shfl_xor_sync(0xffffffffu, rQ[mt][rh], 1);
                rQ[mt][rh] += __shfl_xor_sync(0xffffffffu, rQ[mt][rh], 2);
            }
        if (tq == 0) {
#pragma unroll
            for (int mt = 0; mt < 2; mt++)
#pragma unroll
                for (int rh = 0; rh < 2; rh++) {
                    int node = rb*32 + mt*16 + rh*8 + tr;
                    psumS[node*2 + cg] = rS[mt][rh];
                    psumQ[node*2 + cg] = rQ[mt][rh];
                }
        }
        __syncthreads();

        float muv[2][2], rsv[2][2];
#pragma unroll
        for (int mt = 0; mt < 2; mt++)
#pragma unroll
            for (int rh = 0; rh < 2; rh++) {
                int node = rb*32 + mt*16 + rh*8 + tr;
                float S = psumS[node*2] + psumS[node*2+1];
                float Q = psumQ[node*2] + psumQ[node*2+1];
                float mu = S * (1.0f/128.0f);
                muv[mt][rh] = mu;
                rsv[mt][rh] = rsqrtf(Q * (1.0f/128.0f) - mu*mu + 1e-5f);
            }

        if (layer == 0) {
#pragma unroll
            for (int mt = 0; mt < 2; mt++) {
#pragma unroll
                for (int nt = 0; nt < 8; nt++) {
                    int col0 = ob + nt*8 + 2*tq;
                    float2 gg = *reinterpret_cast<const float2*>(&par[128 + col0]);
                    float2 bb = *reinterpret_cast<const float2*>(&par[256 + col0]);
                    int row0 = rb*32 + mt*16 + tr;
                    float v00 = fmaxf((acc[mt][nt][0]-muv[mt][0])*rsv[mt][0]*gg.x + bb.x, 0.f);
                    float v01 = fmaxf((acc[mt][nt][1]-muv[mt][0])*rsv[mt][0]*gg.y + bb.y, 0.f);
                    float v10 = fmaxf((acc[mt][nt][2]-muv[mt][1])*rsv[mt][1]*gg.x + bb.x, 0.f);
                    float v11 = fmaxf((acc[mt][nt][3]-muv[mt][1])*rsv[mt][1]*gg.y + bb.y, 0.f);
                    uint32_t off0 = (uint32_t)row0 * ASTR_B + col0*2;
                    uint32_t off1 = off0 + 8*ASTR_B;
                    *reinterpret_cast<uint32_t*>(smc + AH_B + off0) = pack2(v00, v01);
                    *reinterpret_cast<uint32_t*>(smc + AH_B + off1) = pack2(v10, v11);
                    *reinterpret_cast<uint32_t*>(smc + AL_B + off0) = pack2(v00 - bfr(v00), v01 - bfr(v01));
                    *reinterpret_cast<uint32_t*>(smc + AL_B + off1) = pack2(v10 - bfr(v10), v11 - bfr(v11));
                }
            }
            __syncthreads();
        } else {
            float cm[8][2];
#pragma unroll
            for (int nt = 0; nt < 8; nt++) { cm[nt][0] = -INFINITY; cm[nt][1] = -INFINITY; }
#pragma unroll
            for (int mt = 0; mt < 2; mt++) {
#pragma unroll
                for (int nt = 0; nt < 8; nt++) {
                    int col0 = ob + nt*8 + 2*tq;
                    float2 gg = *reinterpret_cast<const float2*>(&par[128 + col0]);
                    float2 bb = *reinterpret_cast<const float2*>(&par[256 + col0]);
                    float v00 = fmaxf((acc[mt][nt][0]-muv[mt][0])*rsv[mt][0]*gg.x + bb.x, 0.f);
                    float v01 = fmaxf((acc[mt][nt][1]-muv[mt][0])*rsv[mt][0]*gg.y + bb.y, 0.f);
                    float v10 = fmaxf((acc[mt][nt][2]-muv[mt][1])*rsv[mt][1]*gg.x + bb.x, 0.f);
                    float v11 = fmaxf((acc[mt][nt][3]-muv[mt][1])*rsv[mt][1]*gg.y + bb.y, 0.f);
                    cm[nt][0] = fmaxf(cm[nt][0], fmaxf(v00, v10));
                    cm[nt][1] = fmaxf(cm[nt][1], fmaxf(v01, v11));
                }
            }
#pragma unroll
            for (int nt = 0; nt < 8; nt++)
#pragma unroll
                for (int q = 0; q < 2; q++) {
                    cm[nt][q] = fmaxf(cm[nt][q], __shfl_xor_sync(0xffffffffu, cm[nt][q], 4));
                    cm[nt][q] = fmaxf(cm[nt][q], __shfl_xor_sync(0xffffffffu, cm[nt][q], 8));
                    cm[nt][q] = fmaxf(cm[nt][q], __shfl_xor_sync(0xffffffffu, cm[nt][q], 16));
                }
            if (tr == 0) {
#pragma unroll
                for (int nt = 0; nt < 8; nt++) {
                    wmax[w*64 + nt*8 + 2*tq]     = cm[nt][0];
                    wmax[w*64 + nt*8 + 2*tq + 1] = cm[nt][1];
                }
            }
        }
    }
    __syncthreads();

    // ---- final reduce ----
    if (tid < 128) {
        int cgd = tid >> 6, dd = tid & 63;
        float m = -INFINITY;
#pragma unroll
        for (int i = 0; i < 8; i++) m = fmaxf(m, wmax[(cgd*8 + i)*64 + dd]);
        out[(size_t)bm * 256 + cgd*64 + dd]       = m;
        out[(size_t)bm * 256 + 128 + cgd*64 + dd] = m;
    }
}

extern "C" void kernel_launch(void* const* d_in, const int* in_sizes, int n_in,
                              void* d_out, int out_size)
{
    const int INPUT_ELEMS = 8 * 128 * 256 * 8;   // 2,097,152
    const float* inp = nullptr;
    const float* wt[16];
    int wi = 0;
    for (int i = 0; i < n_in; i++) {
        if (in_sizes[i] == INPUT_ELEMS) inp = (const float*)d_in[i];
        else if (wi < 16)               wt[wi++] = (const float*)d_in[i];
    }
    // wt order: W0 b0 g0 be0 | W1 b1 g1 be1 | W2 b2 g2 be2 | W3 b3 g3 be3

    prep_weights_kernel<<<64, 256>>>(wt[4], wt[8], wt[12]);

    cudaFuncSetAttribute(localgraph_fused_kernel,
                         cudaFuncAttributeMaxDynamicSharedMemorySize, SMEM_BYTES);

    localgraph_fused_kernel<<<8 * 128, NTHREADS, SMEM_BYTES>>>(
        inp,
        wt[0],  wt[1],  wt[2],  wt[3],
        wt[5],  wt[6],  wt[7],
        wt[9],  wt[10], wt[11],
        wt[13], wt[14], wt[15],
        (float*)d_out);
}

// round 17
// speedup vs baseline: 1.0378x; 1.0378x over previous
#include <cuda_runtime.h>
#include <cuda_bf16.h>
#include <math.h>
#include <stdint.h>

#define NTHREADS 512
#define SXSTR 68            // fp32 row stride (floats)
#define ASTR_B 272          // bf16 row stride in BYTES (136 bf16; 272%16==0 for ldmatrix)

// ---- byte offsets ----
#define AH_B 0              // A_hi  [256][136] bf16 = 69632 B
#define AL_B 69632          // A_lo
#define WH_B 139264         // W_hi  [128 k-rows][136 bf16] (K-MAJOR); W1_hi rows 0..63 in stage 1
#define WL_B 174080         // W_lo  (ends 208896)
// ---- float offsets ----
#define SX_F   34816        // fp32 [256][68] overlay on W region (written AFTER W1 reads complete)
#define PAR2_F 52224        // b2|g2|be2 (384 floats)
#define PAR3_F 52608        // b3|g3|be3
#define SRED_F 52992        // 1536: top2 partials / LN psums; pstg (896) aliases this in stage 1
#define SFIN_F 54528        // 192: final top-2 per channel
#define WMAX_F 54720        // 1024: per-warp column maxima
#define SMEM_FLOATS 55744
#define SMEM_BYTES (SMEM_FLOATS*4)   // 222976 — identical to passing R13

__device__ __forceinline__ uint32_t smem_u32(const void* p) {
    uint32_t a;
    asm("{ .reg .u64 t; cvta.to.shared.u64 t, %1; cvt.u32.u64 %0, t; }" : "=r"(a) : "l"(p));
    return a;
}
__device__ __forceinline__ void ldm4(uint32_t& r0, uint32_t& r1, uint32_t& r2, uint32_t& r3, uint32_t a) {
    asm volatile("ldmatrix.sync.aligned.m8n8.x4.shared.b16 {%0,%1,%2,%3}, [%4];"
                 : "=r"(r0), "=r"(r1), "=r"(r2), "=r"(r3) : "r"(a));
}
__device__ __forceinline__ void ldm4t(uint32_t& r0, uint32_t& r1, uint32_t& r2, uint32_t& r3, uint32_t a) {
    asm volatile("ldmatrix.sync.aligned.m8n8.x4.trans.shared.b16 {%0,%1,%2,%3}, [%4];"
                 : "=r"(r0), "=r"(r1), "=r"(r2), "=r"(r3) : "r"(a));
}
__device__ __forceinline__ void mma16816(float* c, const uint32_t* A, const uint32_t* B) {
    asm volatile("mma.sync.aligned.m16n8k16.row.col.f32.bf16.bf16.f32 "
                 "{%0,%1,%2,%3},{%4,%5,%6,%7},{%8,%9},{%0,%1,%2,%3};"
                 : "+f"(c[0]), "+f"(c[1]), "+f"(c[2]), "+f"(c[3])
                 : "r"(A[0]), "r"(A[1]), "r"(A[2]), "r"(A[3]), "r"(B[0]), "r"(B[1]));
}
__device__ __forceinline__ uint32_t pack2(float a, float b) {
    __nv_bfloat162 t = __floats2bfloat162_rn(a, b);
    uint32_t r; memcpy(&r, &t, 4); return r;
}
__device__ __forceinline__ float bfr(float v) {
    return __bfloat162float(__float2bfloat16(v));
}

__global__ __launch_bounds__(NTHREADS, 1)
void localgraph_fused_kernel(
    const float* __restrict__ inp,
    const float* __restrict__ W0, const float* __restrict__ b0, const float* __restrict__ g0, const float* __restrict__ be0,
    const float* __restrict__ W1, const float* __restrict__ b1, const float* __restrict__ g1, const float* __restrict__ be1,
    const float* __restrict__ W2, const float* __restrict__ b2, const float* __restrict__ g2, const float* __restrict__ be2,
    const float* __restrict__ W3, const float* __restrict__ b3, const float* __restrict__ g3, const float* __restrict__ be3,
    float* __restrict__ out)
{
    extern __shared__ float smem[];
    char*  smc  = reinterpret_cast<char*>(smem);
    float* sx   = smem + SX_F;          // [256][68] fp32
    float* pstg = smem + SRED_F;        // stage-1 weights/params (aliases sred; dead before top-2)
    float* par2 = smem + PAR2_F;
    float* par3 = smem + PAR3_F;
    float* sred = smem + SRED_F;
    float* sfin = smem + SFIN_F;
    float* wmax = smem + WMAX_F;

    const uint32_t smb = smem_u32(smem);
    const int tid  = threadIdx.x;
    const int bm   = blockIdx.x;
    const int lane = tid & 31;
    const int w    = tid >> 5;
    const int lg = lane >> 3, lr = lane & 7;
    const int tq = lane & 3, tr = lane >> 2;

    // ======== STAGE 1 staging ========
    for (int i = tid; i < 512; i += NTHREADS) pstg[i] = W0[i];
    if (tid < 64) { pstg[512+tid]=b0[tid]; pstg[576+tid]=g0[tid]; pstg[640+tid]=be0[tid]; }
    if (tid >= 64 && tid < 128) {
        int i = tid - 64;
        pstg[704+i]=b1[i]; pstg[768+i]=g1[i]; pstg[832+i]=be1[i];
    }
    {   // W1 [k=64][o=64]: 1024 float4
        const float4* W1g = reinterpret_cast<const float4*>(W1);
        for (int i = tid; i < 1024; i += NTHREADS) {
            int k = i >> 4, o4 = i & 15;
            float4 v = W1g[i];
            uint32_t off = (uint32_t)k * ASTR_B + o4 * 8;
            *reinterpret_cast<uint2*>(smc + WH_B + off) =
                make_uint2(pack2(v.x, v.y), pack2(v.z, v.w));
            *reinterpret_cast<uint2*>(smc + WL_B + off) =
                make_uint2(pack2(v.x - bfr(v.x), v.y - bfr(v.y)),
                           pack2(v.z - bfr(v.z), v.w - bfr(v.w)));
        }
    }

    // stage-1 scalar decomposition: warp w owns nodes 16w..16w+15
    const int sg  = lane >> 3;
    const int so8 = lane & 7;
    const int sco = 4 * so8;
    const int nb  = 16 * w + sg;        // thread's nodes: nb + 4j

    float x[4][8];
#pragma unroll
    for (int j = 0; j < 4; j++) {
        const float4* pa = reinterpret_cast<const float4*>(inp + ((size_t)bm * 256 + nb + 4*j) * 8);
        float4 a = pa[0], b = pa[1];
        x[j][0]=a.x; x[j][1]=a.y; x[j][2]=a.z; x[j][3]=a.w;
        x[j][4]=b.x; x[j][5]=b.y; x[j][6]=b.z; x[j][7]=b.w;
    }
    __syncthreads();

    // ---- mlp0 (scalar): 8 -> 64, LN, ReLU -> bf16 A hi/lo cols 0..63 ----
    {
        float h[4][8];
#pragma unroll
        for (int G = 0; G < 2; G++) {
            float4 b4 = *reinterpret_cast<const float4*>(&pstg[512 + 32*G + sco]);
#pragma unroll
            for (int j = 0; j < 4; j++) {
                h[j][4*G+0]=b4.x; h[j][4*G+1]=b4.y; h[j][4*G+2]=b4.z; h[j][4*G+3]=b4.w;
            }
        }
#pragma unroll
        for (int k = 0; k < 8; k++) {
#pragma unroll
            for (int G = 0; G < 2; G++) {
                float4 wv = *reinterpret_cast<const float4*>(&pstg[k*64 + 32*G + sco]);
#pragma unroll
                for (int j = 0; j < 4; j++) {
                    float a = x[j][k];
                    h[j][4*G+0] += a*wv.x; h[j][4*G+1] += a*wv.y;
                    h[j][4*G+2] += a*wv.z; h[j][4*G+3] += a*wv.w;
                }
            }
        }
#pragma unroll
        for (int j = 0; j < 4; j++) {
            float sU = 0.f;
#pragma unroll
            for (int i = 0; i < 8; i++) sU += h[j][i];
            sU += __shfl_xor_sync(0xffffffffu, sU, 1);
            sU += __shfl_xor_sync(0xffffffffu, sU, 2);
            sU += __shfl_xor_sync(0xffffffffu, sU, 4);
            float mu = sU * (1.0f/64.0f), vv = 0.f;
#pragma unroll
            for (int i = 0; i < 8; i++) { float d = h[j][i]-mu; vv += d*d; }
            vv += __shfl_xor_sync(0xffffffffu, vv, 1);
            vv += __shfl_xor_sync(0xffffffffu, vv, 2);
            vv += __shfl_xor_sync(0xffffffffu, vv, 4);
            float rs = rsqrtf(vv * (1.0f/64.0f) + 1e-5f);
            uint32_t rowoff = (uint32_t)(nb + 4*j) * ASTR_B;
#pragma unroll
            for (int G = 0; G < 2; G++) {
                float4 g4  = *reinterpret_cast<const float4*>(&pstg[576 + 32*G + sco]);
                float4 be4 = *reinterpret_cast<const float4*>(&pstg[640 + 32*G + sco]);
                float v0 = fmaxf((h[j][4*G+0]-mu)*rs*g4.x + be4.x, 0.f);
                float v1 = fmaxf((h[j][4*G+1]-mu)*rs*g4.y + be4.y, 0.f);
                float v2 = fmaxf((h[j][4*G+2]-mu)*rs*g4.z + be4.z, 0.f);
                float v3 = fmaxf((h[j][4*G+3]-mu)*rs*g4.w + be4.w, 0.f);
                uint32_t off = rowoff + (32*G + sco) * 2;
                *reinterpret_cast<uint2*>(smc + AH_B + off) =
                    make_uint2(pack2(v0, v1), pack2(v2, v3));
                *reinterpret_cast<uint2*>(smc + AL_B + off) =
                    make_uint2(pack2(v0 - bfr(v0), v1 - bfr(v1)),
                               pack2(v2 - bfr(v2), v3 - bfr(v3)));
            }
        }
    }
    __syncthreads();   // A cols 0..63 + W1 visible to all

    // ---- mlp1 (tensor): 64 -> 64, split-bf16; warp owns 16 nodes x 64 cols ----
    {
        const uint32_t aoff1 = smb + AH_B + (uint32_t)(16*w + ((lg&1)<<3) + lr) * ASTR_B + ((lg>>1)<<4);
        const uint32_t boff1 = smb + WH_B + (uint32_t)(((lg&1)<<3) + lr) * ASTR_B + ((lg>>1)<<4);
        float acc1[8][4];
#pragma unroll
        for (int nt = 0; nt < 8; nt++)
#pragma unroll
            for (int q = 0; q < 4; q++) acc1[nt][q] = 0.f;

#pragma unroll
        for (int ks = 0; ks < 4; ks++) {
            const uint32_t kb  = (uint32_t)ks * 32;
            const uint32_t kbw = (uint32_t)ks * 16 * ASTR_B;
            uint32_t Ah[4], Al[4];
            ldm4(Ah[0], Ah[1], Ah[2], Ah[3], aoff1 + kb);
            ldm4(Al[0], Al[1], Al[2], Al[3], aoff1 + (AL_B - AH_B) + kb);
#pragma unroll
            for (int p = 0; p < 4; p++) {
                uint32_t Bh[4], Bl[4];
                ldm4t(Bh[0], Bh[1], Bh[2], Bh[3], boff1 + kbw + (uint32_t)p*32);
                ldm4t(Bl[0], Bl[1], Bl[2], Bl[3], boff1 + (WL_B - WH_B) + kbw + (uint32_t)p*32);
                mma16816(acc1[2*p],   Ah, Bh);
                mma16816(acc1[2*p],   Ah, Bl);
                mma16816(acc1[2*p],   Al, Bh);
                mma16816(acc1[2*p+1], Ah, Bh + 2);
                mma16816(acc1[2*p+1], Ah, Bl + 2);
                mma16816(acc1[2*p+1], Al, Bh + 2);
            }
        }
        __syncthreads();   // ALL warps done reading W1 before sx (overlapping region) is written

        // epilogue: bias + LN (warp-local rows) + ReLU -> fp32 sx AND bf16 A
        float rS[2] = {0.f, 0.f}, rQ[2] = {0.f, 0.f};
#pragma unroll
        for (int nt = 0; nt < 8; nt++) {
            int col0 = nt*8 + 2*tq;
            float2 bb = *reinterpret_cast<const float2*>(&pstg[704 + col0]);
            float v00 = acc1[nt][0] + bb.x, v01 = acc1[nt][1] + bb.y;
            float v10 = acc1[nt][2] + bb.x, v11 = acc1[nt][3] + bb.y;
            acc1[nt][0]=v00; acc1[nt][1]=v01; acc1[nt][2]=v10; acc1[nt][3]=v11;
            rS[0]+=v00+v01; rS[1]+=v10+v11;
            rQ[0]+=v00*v00+v01*v01; rQ[1]+=v10*v10+v11*v11;
        }
#pragma unroll
        for (int rh = 0; rh < 2; rh++) {
            rS[rh] += __shfl_xor_sync(0xffffffffu, rS[rh], 1);
            rS[rh] += __shfl_xor_sync(0xffffffffu, rS[rh], 2);
            rQ[rh] += __shfl_xor_sync(0xffffffffu, rQ[rh], 1);
            rQ[rh] += __shfl_xor_sync(0xffffffffu, rQ[rh], 2);
        }
        float muv[2], rsv[2];
#pragma unroll
        for (int rh = 0; rh < 2; rh++) {
            float mu = rS[rh] * (1.0f/64.0f);
            muv[rh] = mu;
            rsv[rh] = rsqrtf(rQ[rh] * (1.0f/64.0f) - mu*mu + 1e-5f);
        }
        int node0 = 16*w + tr, node1 = node0 + 8;
#pragma unroll
        for (int nt = 0; nt < 8; nt++) {
            int col0 = nt*8 + 2*tq;
            float2 gg = *reinterpret_cast<const float2*>(&pstg[768 + col0]);
            float2 bb = *reinterpret_cast<const float2*>(&pstg[832 + col0]);
            float v00 = fmaxf((acc1[nt][0]-muv[0])*rsv[0]*gg.x + bb.x, 0.f);
            float v01 = fmaxf((acc1[nt][1]-muv[0])*rsv[0]*gg.y + bb.y, 0.f);
            float v10 = fmaxf((acc1[nt][2]-muv[1])*rsv[1]*gg.x + bb.x, 0.f);
            float v11 = fmaxf((acc1[nt][3]-muv[1])*rsv[1]*gg.y + bb.y, 0.f);
            *reinterpret_cast<float2*>(&sx[node0*SXSTR + col0]) = make_float2(v00, v01);
            *reinterpret_cast<float2*>(&sx[node1*SXSTR + col0]) = make_float2(v10, v11);
            uint32_t off0 = (uint32_t)node0 * ASTR_B + col0*2;
            uint32_t off1 = (uint32_t)node1 * ASTR_B + col0*2;
            *reinterpret_cast<uint32_t*>(smc + AH_B + off0) = pack2(v00, v01);
            *reinterpret_cast<uint32_t*>(smc + AH_B + off1) = pack2(v10, v11);
            *reinterpret_cast<uint32_t*>(smc + AL_B + off0) = pack2(v00 - bfr(v00), v01 - bfr(v01));
            *reinterpret_cast<uint32_t*>(smc + AL_B + off1) = pack2(v10 - bfr(v10), v11 - bfr(v11));
        }
    }
    __syncthreads();

    // ---- top-2 + argmax per channel over 256 nodes (reads fp32 sx) ----
    {
        const int ch = tid & 63, chunk = tid >> 6;
        float m1 = -INFINITY, m2 = -INFINITY; int i1 = -1;
        const int jb = chunk * 32;
        for (int j = 0; j < 32; j++) {
            float v = sx[(jb + j) * SXSTR + ch];
            if (v > m1)      { m2 = m1; m1 = v; i1 = jb + j; }
            else if (v > m2) { m2 = v; }
        }
        sred[chunk * 64 + ch]       = m1;
        sred[512 + chunk * 64 + ch] = m2;
        reinterpret_cast<int*>(sred)[1024 + chunk * 64 + ch] = i1;
    }
    __syncthreads();
    if (tid < 64) {
        float m1 = sred[tid], m2 = sred[512 + tid];
        int   i1 = reinterpret_cast<int*>(sred)[1024 + tid];
#pragma unroll
        for (int c = 1; c < 8; c++) {
            float a1 = sred[c * 64 + tid], a2 = sred[512 + c * 64 + tid];
            int   ai = reinterpret_cast<int*>(sred)[1024 + c * 64 + tid];
            if (a1 > m1) { m2 = fmaxf(m1, a2); m1 = a1; i1 = ai; }
            else         { m2 = fmaxf(m2, a1); }
        }
        sfin[tid] = m1; sfin[64 + tid] = m2;
        reinterpret_cast<int*>(sfin)[128 + tid] = i1;
    }
    __syncthreads();

    // ---- concat (excl half only): A cols 64..127 ----
    {
        const int crow = tid >> 1, chalf = tid & 1;
        const float* sr = sx + crow * SXSTR;
        const int cb = chalf * 32;
        char* ah = smc + AH_B + crow * ASTR_B + (64 + cb) * 2;
        char* al = smc + AL_B + crow * ASTR_B + (64 + cb) * 2;
#pragma unroll
        for (int c = 0; c < 32; c += 2) {
            int d = cb + c;
            float a0 = sr[d], a1 = sr[d+1];
            int   j0 = reinterpret_cast<int*>(sfin)[128 + d];
            int   j1 = reinterpret_cast<int*>(sfin)[128 + d + 1];
            float e0x = (j0 == crow) ? sfin[64 + d]     : sfin[d];
            float e1x = (j1 == crow) ? sfin[64 + d + 1] : sfin[d + 1];
            float v0 = fmaxf(e0x, a0 - 10000.0f);
            float v1 = fmaxf(e1x, a1 - 10000.0f);
            *reinterpret_cast<uint32_t*>(ah + c*2) = pack2(v0, v1);
            *reinterpret_cast<uint32_t*>(al + c*2) = pack2(v0 - bfr(v0), v1 - bfr(v1));
        }
    }
    __syncthreads();   // sx consumed; full A ready

    // ======== big layers: warp = (rb = w&7 node-block, cg = w>>3 col-group) ========
    const int rb = w & 7, cg = w >> 3, ob = cg * 64;
    const uint32_t aoff = smb + AH_B + (uint32_t)(rb*32 + ((lg&1)<<3) + lr) * ASTR_B + ((lg>>1)<<4);
    const uint32_t boff = smb + WH_B + (uint32_t)(((lg&1)<<3) + lr) * ASTR_B + (uint32_t)(ob*2 + ((lg>>1)<<4));
    float* psumS = sred;          // [512]
    float* psumQ = sred + 512;    // [512]

    float acc[2][8][4];

    for (int layer = 0; layer < 2; layer++) {
        const float* par = layer ? par3 : par2;
        // ---- layer 0 only: stage W2 (sx dead; W region free) ----
        if (layer == 0) {
            const float4* Wg4 = reinterpret_cast<const float4*>(W2);
            for (int i = tid; i < 4096; i += NTHREADS) {
                int k = i >> 5, o4 = i & 31;
                float4 v = Wg4[i];
                uint32_t off = (uint32_t)k * ASTR_B + o4 * 8;
                *reinterpret_cast<uint2*>(smc + WH_B + off) =
                    make_uint2(pack2(v.x, v.y), pack2(v.z, v.w));
                *reinterpret_cast<uint2*>(smc + WL_B + off) =
                    make_uint2(pack2(v.x - bfr(v.x), v.y - bfr(v.y)),
                               pack2(v.z - bfr(v.z), v.w - bfr(v.w)));
            }
            if (tid < 128) { par2[tid]=b2[tid]; par2[128+tid]=g2[tid]; par2[256+tid]=be2[tid]; }
            __syncthreads();
        }
        // (layer 1 entry is protected by the sync at the end of the layer-0 branch)

        // ---- MMA: C[32 nodes][64 outs] via split-bf16 ----
#pragma unroll
        for (int mt = 0; mt < 2; mt++)
#pragma unroll
            for (int nt = 0; nt < 8; nt++)
#pragma unroll
                for (int q = 0; q < 4; q++) acc[mt][nt][q] = 0.f;

        for (int ks = 0; ks < 8; ks++) {
            const uint32_t kb  = (uint32_t)ks * 32;
            const uint32_t kbw = (uint32_t)ks * 16 * ASTR_B;
            uint32_t Ah[2][4], Al[2][4];
            ldm4(Ah[0][0], Ah[0][1], Ah[0][2], Ah[0][3], aoff + kb);
            ldm4(Ah[1][0], Ah[1][1], Ah[1][2], Ah[1][3], aoff + 16*ASTR_B + kb);
            ldm4(Al[0][0], Al[0][1], Al[0][2], Al[0][3], aoff + (AL_B - AH_B) + kb);
            ldm4(Al[1][0], Al[1][1], Al[1][2], Al[1][3], aoff + (AL_B - AH_B) + 16*ASTR_B + kb);
#pragma unroll
            for (int p = 0; p < 4; p++) {
                uint32_t Bh[4], Bl[4];
                ldm4t(Bh[0], Bh[1], Bh[2], Bh[3], boff + kbw + (uint32_t)p*32);
                ldm4t(Bl[0], Bl[1], Bl[2], Bl[3], boff + (WL_B - WH_B) + kbw + (uint32_t)p*32);
#pragma unroll
                for (int mt = 0; mt < 2; mt++) {
                    mma16816(acc[mt][2*p],   Ah[mt], Bh);
                    mma16816(acc[mt][2*p],   Ah[mt], Bl);
                    mma16816(acc[mt][2*p],   Al[mt], Bh);
                    mma16816(acc[mt][2*p+1], Ah[mt], Bh + 2);
                    mma16816(acc[mt][2*p+1], Ah[mt], Bl + 2);
                    mma16816(acc[mt][2*p+1], Al[mt], Bh + 2);
                }
            }
        }

        // ---- epilogue: bias, LN partial sums ----
        float rS[2][2] = {{0.f,0.f},{0.f,0.f}}, rQ[2][2] = {{0.f,0.f},{0.f,0.f}};
#pragma unroll
        for (int mt = 0; mt < 2; mt++) {
#pragma unroll
            for (int nt = 0; nt < 8; nt++) {
                int col0 = ob + nt*8 + 2*tq;
                float2 bb = *reinterpret_cast<const float2*>(&par[col0]);
                float v00 = acc[mt][nt][0] + bb.x, v01 = acc[mt][nt][1] + bb.y;
                float v10 = acc[mt][nt][2] + bb.x, v11 = acc[mt][nt][3] + bb.y;
                acc[mt][nt][0]=v00; acc[mt][nt][1]=v01; acc[mt][nt][2]=v10; acc[mt][nt][3]=v11;
                rS[mt][0]+=v00+v01; rS[mt][1]+=v10+v11;
                rQ[mt][0]+=v00*v00+v01*v01; rQ[mt][1]+=v10*v10+v11*v11;
            }
        }
#pragma unroll
        for (int mt = 0; mt < 2; mt++)
#pragma unroll
            for (int rh = 0; rh < 2; rh++) {
                rS[mt][rh] += __shfl_xor_sync(0xffffffffu, rS[mt][rh], 1);
                rS[mt][rh] += __shfl_xor_sync(0xffffffffu, rS[mt][rh], 2);
                rQ[mt][rh] += __shfl_xor_sync(0xffffffffu, rQ[mt][rh], 1);
                rQ[mt][rh] += __shfl_xor_sync(0xffffffffu, rQ[mt][rh], 2);
            }
        if (tq == 0) {
#pragma unroll
            for (int mt = 0; mt < 2; mt++)
#pragma unroll
                for (int rh = 0; rh < 2; rh++) {
                    int node = rb*32 + mt*16 + rh*8 + tr;
                    psumS[node*2 + cg] = rS[mt][rh];
                    psumQ[node*2 + cg] = rQ[mt][rh];
                }
        }
        __syncthreads();   // psums ready; ALL warps done with this layer's W MMAs

        // ---- layer 0 only: stage W3 here; LDG latency overlaps epilogue below ----
        if (layer == 0) {
            const float4* Wg4 = reinterpret_cast<const float4*>(W3);
            for (int i = tid; i < 4096; i += NTHREADS) {
                int k = i >> 5, o4 = i & 31;
                float4 v = Wg4[i];
                uint32_t off = (uint32_t)k * ASTR_B + o4 * 8;
                *reinterpret_cast<uint2*>(smc + WH_B + off) =
                    make_uint2(pack2(v.x, v.y), pack2(v.z, v.w));
                *reinterpret_cast<uint2*>(smc + WL_B + off) =
                    make_uint2(pack2(v.x - bfr(v.x), v.y - bfr(v.y)),
                               pack2(v.z - bfr(v.z), v.w - bfr(v.w)));
            }
            if (tid < 128) { par3[tid]=b3[tid]; par3[128+tid]=g3[tid]; par3[256+tid]=be3[tid]; }
        }

        float muv[2][2], rsv[2][2];
#pragma unroll
        for (int mt = 0; mt < 2; mt++)
#pragma unroll
            for (int rh = 0; rh < 2; rh++) {
                int node = rb*32 + mt*16 + rh*8 + tr;
                float S = psumS[node*2] + psumS[node*2+1];
                float Q = psumQ[node*2] + psumQ[node*2+1];
                float mu = S * (1.0f/128.0f);
                muv[mt][rh] = mu;
                rsv[mt][rh] = rsqrtf(Q * (1.0f/128.0f) - mu*mu + 1e-5f);
            }

        if (layer == 0) {
#pragma unroll
            for (int mt = 0; mt < 2; mt++) {
#pragma unroll
                for (int nt = 0; nt < 8; nt++) {
                    int col0 = ob + nt*8 + 2*tq;
                    float2 gg = *reinterpret_cast<const float2*>(&par[128 + col0]);
                    float2 bb = *reinterpret_cast<const float2*>(&par[256 + col0]);
                    int row0 = rb*32 + mt*16 + tr;
                    float v00 = fmaxf((acc[mt][nt][0]-muv[mt][0])*rsv[mt][0]*gg.x + bb.x, 0.f);
                    float v01 = fmaxf((acc[mt][nt][1]-muv[mt][0])*rsv[mt][0]*gg.y + bb.y, 0.f);
                    float v10 = fmaxf((acc[mt][nt][2]-muv[mt][1])*rsv[mt][1]*gg.x + bb.x, 0.f);
                    float v11 = fmaxf((acc[mt][nt][3]-muv[mt][1])*rsv[mt][1]*gg.y + bb.y, 0.f);
                    uint32_t off0 = (uint32_t)row0 * ASTR_B + col0*2;
                    uint32_t off1 = off0 + 8*ASTR_B;
                    *reinterpret_cast<uint32_t*>(smc + AH_B + off0) = pack2(v00, v01);
                    *reinterpret_cast<uint32_t*>(smc + AH_B + off1) = pack2(v10, v11);
                    *reinterpret_cast<uint32_t*>(smc + AL_B + off0) = pack2(v00 - bfr(v00), v01 - bfr(v01));
                    *reinterpret_cast<uint32_t*>(smc + AL_B + off1) = pack2(v10 - bfr(v10), v11 - bfr(v11));
                }
            }
            __syncthreads();   // A updated + W3/par3 staged -> layer 1 may read both
        } else {
            float cm[8][2];
#pragma unroll
            for (int nt = 0; nt < 8; nt++) { cm[nt][0] = -INFINITY; cm[nt][1] = -INFINITY; }
#pragma unroll
            for (int mt = 0; mt < 2; mt++) {
#pragma unroll
                for (int nt = 0; nt < 8; nt++) {
                    int col0 = ob + nt*8 + 2*tq;
                    float2 gg = *reinterpret_cast<const float2*>(&par[128 + col0]);
                    float2 bb = *reinterpret_cast<const float2*>(&par[256 + col0]);
                    float v00 = fmaxf((acc[mt][nt][0]-muv[mt][0])*rsv[mt][0]*gg.x + bb.x, 0.f);
                    float v01 = fmaxf((acc[mt][nt][1]-muv[mt][0])*rsv[mt][0]*gg.y + bb.y, 0.f);
                    float v10 = fmaxf((acc[mt][nt][2]-muv[mt][1])*rsv[mt][1]*gg.x + bb.x, 0.f);
                    float v11 = fmaxf((acc[mt][nt][3]-muv[mt][1])*rsv[mt][1]*gg.y + bb.y, 0.f);
                    cm[nt][0] = fmaxf(cm[nt][0], fmaxf(v00, v10));
                    cm[nt][1] = fmaxf(cm[nt][1], fmaxf(v01, v11));
                }
            }
#pragma unroll
            for (int nt = 0; nt < 8; nt++)
#pragma unroll
                for (int q = 0; q < 2; q++) {
                    cm[nt][q] = fmaxf(cm[nt][q], __shfl_xor_sync(0xffffffffu, cm[nt][q], 4));
                    cm[nt][q] = fmaxf(cm[nt][q], __shfl_xor_sync(0xffffffffu, cm[nt][q], 8));
                    cm[nt][q] = fmaxf(cm[nt][q], __shfl_xor_sync(0xffffffffu, cm[nt][q], 16));
                }
            if (tr == 0) {
#pragma unroll
                for (int nt = 0; nt < 8; nt++) {
                    wmax[w*64 + nt*8 + 2*tq]     = cm[nt][0];
                    wmax[w*64 + nt*8 + 2*tq + 1] = cm[nt][1];
                }
            }
        }
    }
    __syncthreads();

    // ---- final reduce ----
    if (tid < 128) {
        int cgd = tid >> 6, dd = tid & 63;
        float m = -INFINITY;
#pragma unroll
        for (int i = 0; i < 8; i++) m = fmaxf(m, wmax[(cgd*8 + i)*64 + dd]);
        out[(size_t)bm * 256 + cgd*64 + dd]       = m;
        out[(size_t)bm * 256 + 128 + cgd*64 + dd] = m;
    }
}

extern "C" void kernel_launch(void* const* d_in, const int* in_sizes, int n_in,
                              void* d_out, int out_size)
{
    const int INPUT_ELEMS = 8 * 128 * 256 * 8;   // 2,097,152
    const float* inp = nullptr;
    const float* wt[16];
    int wi = 0;
    for (int i = 0; i < n_in; i++) {
        if (in_sizes[i] == INPUT_ELEMS) inp = (const float*)d_in[i];
        else if (wi < 16)               wt[wi++] = (const float*)d_in[i];
    }

    cudaFuncSetAttribute(localgraph_fused_kernel,
                         cudaFuncAttributeMaxDynamicSharedMemorySize, SMEM_BYTES);

    localgraph_fused_kernel<<<8 * 128, NTHREADS, SMEM_BYTES>>>(
        inp,
        wt[0],  wt[1],  wt[2],  wt[3],
        wt[4],  wt[5],  wt[6],  wt[7],
        wt[8],  wt[9],  wt[10], wt[11],
        wt[12], wt[13], wt[14], wt[15],
        (float*)d_out);
}